// round 3
// baseline (speedup 1.0000x reference)
#include <cuda_runtime.h>
#include <cstdint>

// ======== fixed problem dims ========
static constexpr int TT = 4096;   // tokens = 2*2048
static constexpr int HH = 1024;
static constexpr int FF = 4096;
static constexpr int EE = 8;

// ======== device scratch (no allocation allowed) ========
__device__ int   g_cnt[EE];
__device__ int   g_perm[EE * TT];
__device__ float g_gate[EE * TT];
__device__ float g_h[(size_t)EE * TT * FF];   // 512 MB intermediate

#define DEVI __device__ __forceinline__

DEVI uint32_t smem_u32(const void* p) {
    uint32_t a;
    asm("{ .reg .u64 t; cvta.to.shared.u64 t, %1; cvt.u32.u64 %0, t; }" : "=r"(a) : "l"(p));
    return a;
}

// load fp32 from swizzled smem tile, round to tf32 (rna kills truncation bias)
DEVI uint32_t lds_tf32(uint32_t base, int r, int c) {
    uint32_t addr = base + (uint32_t)r * 128u + ((((uint32_t)c >> 2) ^ ((uint32_t)r & 7u)) << 4) + (((uint32_t)c & 3u) << 2);
    uint32_t v;
    asm volatile("ld.shared.b32 %0, [%1];" : "=r"(v) : "r"(addr));
    asm("cvt.rna.tf32.f32 %0, %0;" : "+r"(v));
    return v;
}

DEVI void mma8(float* d, const uint32_t* a, uint32_t b0, uint32_t b1) {
    asm volatile(
        "mma.sync.aligned.m16n8k8.row.col.f32.tf32.tf32.f32 "
        "{%0,%1,%2,%3}, {%4,%5,%6,%7}, {%8,%9}, {%0,%1,%2,%3};"
        : "+f"(d[0]), "+f"(d[1]), "+f"(d[2]), "+f"(d[3])
        : "r"(a[0]), "r"(a[1]), "r"(a[2]), "r"(a[3]), "r"(b0), "r"(b1));
}

DEVI void cp16(uint32_t dst, const void* src) {
    asm volatile("cp.async.cg.shared.global [%0], [%1], 16;" :: "r"(dst), "l"(src) : "memory");
}
#define CP_COMMIT() asm volatile("cp.async.commit_group;" ::: "memory")
#define CP_WAIT1()  asm volatile("cp.async.wait_group 1;" ::: "memory")

DEVI float silu(float v) { return v / (1.f + __expf(-v)); }

// ======== kernel 0: zero expert counters ========
__global__ void moe_zero() {
    if (threadIdx.x < EE) g_cnt[threadIdx.x] = 0;
}

// ======== kernel 1: router ========
__global__ void __launch_bounds__(128) moe_router(
    const float* __restrict__ x, const float* __restrict__ wr, float* __restrict__ logits)
{
    __shared__ float swr[EE * HH];   // transposed: swr[col*8 + e]
    for (int i = threadIdx.x; i < EE * HH; i += 128) {
        int col = i >> 3, e = i & 7;
        swr[i] = wr[e * HH + col];
    }
    __syncthreads();

    int nwarp = gridDim.x * 4;
    int warp  = blockIdx.x * 4 + (threadIdx.x >> 5);
    int lane  = threadIdx.x & 31;

    for (int t = warp; t < TT; t += nwarp) {
        float acc[EE];
#pragma unroll
        for (int e = 0; e < EE; e++) acc[e] = 0.f;
        const float4* xr = (const float4*)(x + (size_t)t * HH);
        for (int i = lane; i < HH / 4; i += 32) {
            float4 v = xr[i];
            int c = i * 4;
#pragma unroll
            for (int e = 0; e < EE; e++)
                acc[e] += v.x * swr[(c + 0) * 8 + e] + v.y * swr[(c + 1) * 8 + e]
                        + v.z * swr[(c + 2) * 8 + e] + v.w * swr[(c + 3) * 8 + e];
        }
#pragma unroll
        for (int e = 0; e < EE; e++) {
#pragma unroll
            for (int o = 16; o > 0; o >>= 1)
                acc[e] += __shfl_xor_sync(0xffffffffu, acc[e], o);
        }
        if (lane == 0) {
            float mx = acc[0];
#pragma unroll
            for (int e = 1; e < EE; e++) mx = fmaxf(mx, acc[e]);
            float p[EE];
#pragma unroll
            for (int e = 0; e < EE; e++) p[e] = __expf(acc[e] - mx);
            int e0 = 0;
#pragma unroll
            for (int e = 1; e < EE; e++) if (p[e] > p[e0]) e0 = e;
            int e1 = (e0 == 0) ? 1 : 0;
#pragma unroll
            for (int e = 0; e < EE; e++) if (e != e0 && p[e] > p[e1]) e1 = e;
            float ws = p[e0] + p[e1];
            float w0 = p[e0] / ws, w1v = p[e1] / ws;
#pragma unroll
            for (int e = 0; e < EE; e++) logits[(size_t)t * EE + e] = acc[e];
            int q0 = atomicAdd(&g_cnt[e0], 1);
            g_perm[e0 * TT + q0] = t; g_gate[e0 * TT + q0] = w0;
            int q1 = atomicAdd(&g_cnt[e1], 1);
            g_perm[e1 * TT + q1] = t; g_gate[e1 * TT + q1] = w1v;
        }
    }
}

// ======== GEMM1: h = silu(X w1^T) * (X w3^T) ========
// block tile 128(M tokens, gathered) x 128(F), K=HH in 32-chunks, cp.async 3 stages.
// 256 threads = 8 warps as 2(M) x 4(N); warp tile 64x32 per B matrix, dual accum.
static constexpr int G1_STAGE = 3 * 16384;           // A + B1 + B3
static constexpr int SMEM1 = 3 * G1_STAGE + 512;     // 147968

DEVI void g1_load(uint32_t sbase, int s, int kc, int tid, const int* s_tok,
                  const float* x, const float* w1r, const float* w3r)
{
    uint32_t st = sbase + (uint32_t)s * G1_STAGE;
#pragma unroll
    for (int p = 0; p < 4; p++) {
        int idx = tid + 256 * p;
        int row = idx >> 3, ch = idx & 7;
        uint32_t sw = ((uint32_t)(ch ^ (row & 7))) << 4;
        const char* srcA = (const char*)(x + (size_t)s_tok[row] * HH) + kc * 128 + ch * 16;
        cp16(st + (uint32_t)row * 128u + sw, srcA);
        const char* src1 = (const char*)(w1r + (size_t)row * HH) + kc * 128 + ch * 16;
        cp16(st + 16384u + (uint32_t)row * 128u + sw, src1);
        const char* src3 = (const char*)(w3r + (size_t)row * HH) + kc * 128 + ch * 16;
        cp16(st + 32768u + (uint32_t)row * 128u + sw, src3);
    }
}

__global__ void __launch_bounds__(256) moe_gemm1(
    const float* __restrict__ x, const float* __restrict__ w1, const float* __restrict__ w3)
{
    int e   = blockIdx.z;
    int cnt = g_cnt[e];
    int m0  = blockIdx.x * 128;
    if (m0 >= cnt) return;
    int f0  = blockIdx.y * 128;

    extern __shared__ char sm[];
    uint32_t sbase = smem_u32(sm);
    int* s_tok = (int*)(sm + 3 * G1_STAGE);

    int tid = threadIdx.x, wid = tid >> 5, lane = tid & 31;
    int wm = wid & 1, wn = wid >> 1;

    if (tid < 128) {
        int slot = m0 + tid;
        s_tok[tid] = g_perm[e * TT + (slot < cnt ? slot : 0)];
    }
    __syncthreads();

    const float* w1r = w1 + (size_t)e * FF * HH + (size_t)f0 * HH;
    const float* w3r = w3 + (size_t)e * FF * HH + (size_t)f0 * HH;

    g1_load(sbase, 0, 0, tid, s_tok, x, w1r, w3r);
    CP_COMMIT();
    g1_load(sbase, 1, 1, tid, s_tok, x, w1r, w3r);
    CP_COMMIT();

    float c1[4][4][4], c3[4][4][4];
#pragma unroll
    for (int i = 0; i < 4; i++)
#pragma unroll
        for (int j = 0; j < 4; j++)
#pragma unroll
            for (int k = 0; k < 4; k++) { c1[i][j][k] = 0.f; c3[i][j][k] = 0.f; }

    int s = 0;
    for (int kc = 0; kc < HH / 32; kc++) {
        CP_WAIT1();
        __syncthreads();
        uint32_t As  = sbase + (uint32_t)s * G1_STAGE;
        uint32_t B1s = As + 16384u;
        uint32_t B3s = As + 32768u;
#pragma unroll
        for (int ks = 0; ks < 4; ks++) {
            int k0 = ks * 8;
            uint32_t a[4][4];
#pragma unroll
            for (int mi = 0; mi < 4; mi++) {
                int r = wm * 64 + mi * 16 + (lane >> 2);
                int c = k0 + (lane & 3);
                a[mi][0] = lds_tf32(As, r,     c);
                a[mi][1] = lds_tf32(As, r + 8, c);
                a[mi][2] = lds_tf32(As, r,     c + 4);
                a[mi][3] = lds_tf32(As, r + 8, c + 4);
            }
#pragma unroll
            for (int ni = 0; ni < 4; ni++) {
                int n = wn * 32 + ni * 8 + (lane >> 2);
                int ck = k0 + (lane & 3);
                uint32_t b0 = lds_tf32(B1s, n, ck);
                uint32_t b1 = lds_tf32(B1s, n, ck + 4);
#pragma unroll
                for (int mi = 0; mi < 4; mi++) mma8(c1[mi][ni], a[mi], b0, b1);
                b0 = lds_tf32(B3s, n, ck);
                b1 = lds_tf32(B3s, n, ck + 4);
#pragma unroll
                for (int mi = 0; mi < 4; mi++) mma8(c3[mi][ni], a[mi], b0, b1);
            }
        }
        if (kc + 2 < HH / 32) {
            int s2 = s + 2; if (s2 >= 3) s2 -= 3;
            g1_load(sbase, s2, kc + 2, tid, s_tok, x, w1r, w3r);
        }
        CP_COMMIT();
        if (++s == 3) s = 0;
    }

    // epilogue: silu(p1)*p3 -> g_h
    size_t hrow_base = (size_t)e * TT + m0;
#pragma unroll
    for (int mi = 0; mi < 4; mi++) {
        int lr = wm * 64 + mi * 16 + (lane >> 2);
#pragma unroll
        for (int ni = 0; ni < 4; ni++) {
            int lc = wn * 32 + ni * 8 + (lane & 3) * 2;
            float v0 = silu(c1[mi][ni][0]) * c3[mi][ni][0];
            float v1 = silu(c1[mi][ni][1]) * c3[mi][ni][1];
            float v2 = silu(c1[mi][ni][2]) * c3[mi][ni][2];
            float v3 = silu(c1[mi][ni][3]) * c3[mi][ni][3];
            *(float2*)&g_h[(hrow_base + lr)     * FF + f0 + lc] = make_float2(v0, v1);
            *(float2*)&g_h[(hrow_base + lr + 8) * FF + f0 + lc] = make_float2(v2, v3);
        }
    }
}

// ======== GEMM2: out += gate * (h w2^T) ========
static constexpr int G2_STAGE = 2 * 16384;           // A + B
static constexpr int SMEM2 = 3 * G2_STAGE + 1024;    // 99328

DEVI void g2_load(uint32_t sbase, int s, int kc, int tid,
                  const float* ha, const float* w2r)
{
    uint32_t st = sbase + (uint32_t)s * G2_STAGE;
#pragma unroll
    for (int p = 0; p < 4; p++) {
        int idx = tid + 256 * p;
        int row = idx >> 3, ch = idx & 7;
        uint32_t sw = ((uint32_t)(ch ^ (row & 7))) << 4;
        const char* srcA = (const char*)(ha + (size_t)row * FF) + kc * 128 + ch * 16;
        cp16(st + (uint32_t)row * 128u + sw, srcA);
        const char* srcB = (const char*)(w2r + (size_t)row * FF) + kc * 128 + ch * 16;
        cp16(st + 16384u + (uint32_t)row * 128u + sw, srcB);
    }
}

__global__ void __launch_bounds__(256) moe_gemm2(
    const float* __restrict__ w2, float* __restrict__ out)
{
    int e   = blockIdx.z;
    int cnt = g_cnt[e];
    int m0  = blockIdx.x * 128;
    if (m0 >= cnt) return;
    int h0  = blockIdx.y * 128;

    extern __shared__ char sm[];
    uint32_t sbase = smem_u32(sm);
    int*   s_tok  = (int*)(sm + 3 * G2_STAGE);
    float* s_gate = (float*)(sm + 3 * G2_STAGE + 512);

    int tid = threadIdx.x, wid = tid >> 5, lane = tid & 31;
    int wm = wid & 1, wn = wid >> 1;

    if (tid < 128) {
        int slot = m0 + tid;
        int idx  = e * TT + (slot < cnt ? slot : 0);
        s_tok[tid]  = g_perm[idx];
        s_gate[tid] = g_gate[idx];
    }
    __syncthreads();

    const float* ha  = &g_h[((size_t)e * TT + m0) * FF];
    const float* w2r = w2 + (size_t)e * HH * FF + (size_t)h0 * FF;

    g2_load(sbase, 0, 0, tid, ha, w2r);
    CP_COMMIT();
    g2_load(sbase, 1, 1, tid, ha, w2r);
    CP_COMMIT();

    float cc[4][4][4];
#pragma unroll
    for (int i = 0; i < 4; i++)
#pragma unroll
        for (int j = 0; j < 4; j++)
#pragma unroll
            for (int k = 0; k < 4; k++) cc[i][j][k] = 0.f;

    int s = 0;
    for (int kc = 0; kc < FF / 32; kc++) {
        CP_WAIT1();
        __syncthreads();
        uint32_t As = sbase + (uint32_t)s * G2_STAGE;
        uint32_t Bs = As + 16384u;
#pragma unroll
        for (int ks = 0; ks < 4; ks++) {
            int k0 = ks * 8;
            uint32_t a[4][4];
#pragma unroll
            for (int mi = 0; mi < 4; mi++) {
                int r = wm * 64 + mi * 16 + (lane >> 2);
                int c = k0 + (lane & 3);
                a[mi][0] = lds_tf32(As, r,     c);
                a[mi][1] = lds_tf32(As, r + 8, c);
                a[mi][2] = lds_tf32(As, r,     c + 4);
                a[mi][3] = lds_tf32(As, r + 8, c + 4);
            }
#pragma unroll
            for (int ni = 0; ni < 4; ni++) {
                int n = wn * 32 + ni * 8 + (lane >> 2);
                int ck = k0 + (lane & 3);
                uint32_t b0 = lds_tf32(Bs, n, ck);
                uint32_t b1 = lds_tf32(Bs, n, ck + 4);
#pragma unroll
                for (int mi = 0; mi < 4; mi++) mma8(cc[mi][ni], a[mi], b0, b1);
            }
        }
        if (kc + 2 < FF / 32) {
            int s2 = s + 2; if (s2 >= 3) s2 -= 3;
            g2_load(sbase, s2, kc + 2, tid, ha, w2r);
        }
        CP_COMMIT();
        if (++s == 3) s = 0;
    }

    // epilogue: scatter-add with gate weights (2 commutative adds per element)
#pragma unroll
    for (int mi = 0; mi < 4; mi++) {
        int lr0 = wm * 64 + mi * 16 + (lane >> 2);
        int lr1 = lr0 + 8;
        bool v0 = (m0 + lr0) < cnt, v1 = (m0 + lr1) < cnt;
        int   t0 = s_tok[lr0],  t1 = s_tok[lr1];
        float gg0 = s_gate[lr0], gg1 = s_gate[lr1];
        float* o0 = out + (size_t)t0 * HH + h0;
        float* o1 = out + (size_t)t1 * HH + h0;
#pragma unroll
        for (int ni = 0; ni < 4; ni++) {
            int lc = wn * 32 + ni * 8 + (lane & 3) * 2;
            if (v0) {
                atomicAdd(&o0[lc],     gg0 * cc[mi][ni][0]);
                atomicAdd(&o0[lc + 1], gg0 * cc[mi][ni][1]);
            }
            if (v1) {
                atomicAdd(&o1[lc],     gg1 * cc[mi][ni][2]);
                atomicAdd(&o1[lc + 1], gg1 * cc[mi][ni][3]);
            }
        }
    }
}

// ======== launch ========
extern "C" void kernel_launch(void* const* d_in, const int* in_sizes, int n_in,
                              void* d_out, int out_size)
{
    (void)in_sizes; (void)n_in; (void)out_size;
    const float* x  = (const float*)d_in[0];
    const float* wr = (const float*)d_in[1];
    const float* w1 = (const float*)d_in[2];
    const float* w2 = (const float*)d_in[3];
    const float* w3 = (const float*)d_in[4];
    float* out    = (float*)d_out;                   // [TT*HH] then logits [TT*EE]
    float* logits = out + (size_t)TT * HH;

    cudaFuncSetAttribute(moe_gemm1, cudaFuncAttributeMaxDynamicSharedMemorySize, SMEM1);
    cudaFuncSetAttribute(moe_gemm2, cudaFuncAttributeMaxDynamicSharedMemorySize, SMEM2);

    cudaMemsetAsync(out, 0, (size_t)TT * HH * sizeof(float));
    moe_zero<<<1, 32>>>();
    moe_router<<<64, 128>>>(x, wr, logits);
    moe_gemm1<<<dim3(32, 32, EE), 256, SMEM1>>>(x, w1, w3);
    moe_gemm2<<<dim3(32, 8, EE), 256, SMEM2>>>(w2, out);
}

// round 4
// speedup vs baseline: 1.1379x; 1.1379x over previous
#include <cuda_runtime.h>
#include <cstdint>

// ======== fixed problem dims ========
static constexpr int TT = 4096;
static constexpr int HH = 1024;
static constexpr int FF = 4096;
static constexpr int EE = 8;

// ======== device scratch ========
__device__ int   g_cnt[EE];
__device__ int   g_perm[EE * TT];
__device__ float g_gate[EE * TT];
__device__ float g_xr[(size_t)TT * HH];       // tf32-rounded x
__device__ float g_h[(size_t)EE * TT * FF];   // tf32-rounded intermediate

#define DEVI __device__ __forceinline__

DEVI uint32_t smem_u32(const void* p) {
    uint32_t a;
    asm("{ .reg .u64 t; cvta.to.shared.u64 t, %1; cvt.u32.u64 %0, t; }" : "=r"(a) : "l"(p));
    return a;
}

DEVI void ldsm4(uint32_t* r, uint32_t addr) {
    asm volatile("ldmatrix.sync.aligned.m8n8.x4.shared.b16 {%0,%1,%2,%3}, [%4];"
        : "=r"(r[0]), "=r"(r[1]), "=r"(r[2]), "=r"(r[3]) : "r"(addr));
}
DEVI void cvt4(uint32_t* r) {
#pragma unroll
    for (int i = 0; i < 4; i++) asm("cvt.rna.tf32.f32 %0, %0;" : "+r"(r[i]));
}
DEVI float rnd_tf32(float f) {
    uint32_t u;
    asm("cvt.rna.tf32.f32 %0, %1;" : "=r"(u) : "f"(f));
    return __uint_as_float(u);
}

DEVI void mma8(float* d, const uint32_t* a, uint32_t b0, uint32_t b1) {
    asm volatile(
        "mma.sync.aligned.m16n8k8.row.col.f32.tf32.tf32.f32 "
        "{%0,%1,%2,%3}, {%4,%5,%6,%7}, {%8,%9}, {%0,%1,%2,%3};"
        : "+f"(d[0]), "+f"(d[1]), "+f"(d[2]), "+f"(d[3])
        : "r"(a[0]), "r"(a[1]), "r"(a[2]), "r"(a[3]), "r"(b0), "r"(b1));
}

DEVI void cp16(uint32_t dst, const void* src) {
    asm volatile("cp.async.cg.shared.global [%0], [%1], 16;" :: "r"(dst), "l"(src) : "memory");
}
#define CP_COMMIT() asm volatile("cp.async.commit_group;" ::: "memory")
#define CP_WAIT1()  asm volatile("cp.async.wait_group 1;" ::: "memory")

// swizzled smem address: base + row*128 + ((chunk ^ (row&7))<<4)
DEVI uint32_t smx(uint32_t base, uint32_t rowoff, uint32_t rmask, uint32_t chunk) {
    return base + rowoff + ((chunk ^ rmask) << 4);
}

DEVI float silu(float v) { return v / (1.f + __expf(-v)); }

// ======== kernel 0: zero counters ========
__global__ void moe_zero() {
    if (threadIdx.x < EE) g_cnt[threadIdx.x] = 0;
}

// ======== kernel 0b: pre-round x to tf32 ========
__global__ void __launch_bounds__(256) moe_round_x(const float* __restrict__ x) {
    int i = blockIdx.x * 256 + threadIdx.x;
    float4 v = ((const float4*)x)[i];
    v.x = rnd_tf32(v.x); v.y = rnd_tf32(v.y); v.z = rnd_tf32(v.z); v.w = rnd_tf32(v.w);
    ((float4*)g_xr)[i] = v;
}

// ======== kernel 1: router ========
__global__ void __launch_bounds__(128) moe_router(
    const float* __restrict__ x, const float* __restrict__ wr, float* __restrict__ logits)
{
    __shared__ float swr[EE * HH];
    for (int i = threadIdx.x; i < EE * HH; i += 128) {
        int col = i >> 3, e = i & 7;
        swr[i] = wr[e * HH + col];
    }
    __syncthreads();

    int nwarp = gridDim.x * 4;
    int warp  = blockIdx.x * 4 + (threadIdx.x >> 5);
    int lane  = threadIdx.x & 31;

    for (int t = warp; t < TT; t += nwarp) {
        float acc[EE];
#pragma unroll
        for (int e = 0; e < EE; e++) acc[e] = 0.f;
        const float4* xr = (const float4*)(x + (size_t)t * HH);
        for (int i = lane; i < HH / 4; i += 32) {
            float4 v = xr[i];
            int c = i * 4;
#pragma unroll
            for (int e = 0; e < EE; e++)
                acc[e] += v.x * swr[(c + 0) * 8 + e] + v.y * swr[(c + 1) * 8 + e]
                        + v.z * swr[(c + 2) * 8 + e] + v.w * swr[(c + 3) * 8 + e];
        }
#pragma unroll
        for (int e = 0; e < EE; e++) {
#pragma unroll
            for (int o = 16; o > 0; o >>= 1)
                acc[e] += __shfl_xor_sync(0xffffffffu, acc[e], o);
        }
        if (lane == 0) {
            float mx = acc[0];
#pragma unroll
            for (int e = 1; e < EE; e++) mx = fmaxf(mx, acc[e]);
            float p[EE];
#pragma unroll
            for (int e = 0; e < EE; e++) p[e] = __expf(acc[e] - mx);
            int e0 = 0;
#pragma unroll
            for (int e = 1; e < EE; e++) if (p[e] > p[e0]) e0 = e;
            int e1 = (e0 == 0) ? 1 : 0;
#pragma unroll
            for (int e = 0; e < EE; e++) if (e != e0 && p[e] > p[e1]) e1 = e;
            float ws = p[e0] + p[e1];
            float w0 = p[e0] / ws, w1v = p[e1] / ws;
#pragma unroll
            for (int e = 0; e < EE; e++) logits[(size_t)t * EE + e] = acc[e];
            int q0 = atomicAdd(&g_cnt[e0], 1);
            g_perm[e0 * TT + q0] = t; g_gate[e0 * TT + q0] = w0;
            int q1 = atomicAdd(&g_cnt[e1], 1);
            g_perm[e1 * TT + q1] = t; g_gate[e1 * TT + q1] = w1v;
        }
    }
}

// ======== GEMM1: h = silu(X w1^T) * (X w3^T) ========
// 512 threads, block tile 128x128, warps 4M x 4N, warp tile 32x32 dual accum.
static constexpr int G1_STAGE = 3 * 16384;           // A + B1 + B3
static constexpr int SMEM1 = 3 * G1_STAGE + 512;     // 147968

DEVI void g1_load(uint32_t st, int kc, int tid, const int* s_tok,
                  const float* xr, const float* w1r, const float* w3r)
{
#pragma unroll
    for (int p = 0; p < 6; p++) {
        int within = tid + 512 * (p & 1);
        int row = within >> 3, ch = within & 7;
        uint32_t dst = st + (uint32_t)(p >> 1) * 16384u
                     + (uint32_t)row * 128u + ((uint32_t)(ch ^ (row & 7)) << 4);
        const float* src;
        if (p < 2)      src = xr  + (size_t)s_tok[row] * HH + kc * 32 + ch * 4;
        else if (p < 4) src = w1r + (size_t)row * HH + kc * 32 + ch * 4;
        else            src = w3r + (size_t)row * HH + kc * 32 + ch * 4;
        cp16(dst, src);
    }
}

__global__ void __launch_bounds__(512, 1) moe_gemm1(
    const float* __restrict__ w1, const float* __restrict__ w3)
{
    int e   = blockIdx.z;
    int cnt = g_cnt[e];
    int m0  = blockIdx.x * 128;
    if (m0 >= cnt) return;
    int f0  = blockIdx.y * 128;

    extern __shared__ char sm[];
    uint32_t sbase = smem_u32(sm);
    int* s_tok = (int*)(sm + 3 * G1_STAGE);

    int tid = threadIdx.x, wid = tid >> 5, lane = tid & 31;
    int wm = wid & 3, wn = wid >> 2;

    if (tid < 128) {
        int slot = m0 + tid;
        s_tok[tid] = g_perm[e * TT + (slot < cnt ? slot : 0)];
    }
    __syncthreads();

    const float* w1r = w1 + (size_t)e * FF * HH + (size_t)f0 * HH;
    const float* w3r = w3 + (size_t)e * FF * HH + (size_t)f0 * HH;

    g1_load(sbase, 0, tid, s_tok, g_xr, w1r, w3r);
    CP_COMMIT();
    g1_load(sbase + G1_STAGE, 1, tid, s_tok, g_xr, w1r, w3r);
    CP_COMMIT();

    // ldmatrix per-thread address components
    uint32_t hiA = (uint32_t)(lane >> 4);        // A chunk offset bit
    uint32_t cselB = (uint32_t)((lane >> 3) & 1); // B chunk offset bit
    uint32_t rowA[2], rmA[2], rowB[2], rmB[2];
#pragma unroll
    for (int mi = 0; mi < 2; mi++) {
        int r = wm * 32 + mi * 16 + (lane & 15);
        rowA[mi] = (uint32_t)r * 128u; rmA[mi] = (uint32_t)(r & 7);
    }
#pragma unroll
    for (int p = 0; p < 2; p++) {
        int n = wn * 32 + p * 16 + (lane & 7) + ((lane >> 4) << 3);
        rowB[p] = (uint32_t)n * 128u; rmB[p] = (uint32_t)(n & 7);
    }

    float c1[2][4][4], c3[2][4][4];
#pragma unroll
    for (int i = 0; i < 2; i++)
#pragma unroll
        for (int j = 0; j < 4; j++)
#pragma unroll
            for (int k = 0; k < 4; k++) { c1[i][j][k] = 0.f; c3[i][j][k] = 0.f; }

    int s = 0;
    for (int kc = 0; kc < HH / 32; kc++) {
        CP_WAIT1();
        __syncthreads();
        uint32_t As  = sbase + (uint32_t)s * G1_STAGE;
        uint32_t B1s = As + 16384u;
        uint32_t B3s = As + 32768u;
#pragma unroll
        for (int ks = 0; ks < 4; ks++) {
            uint32_t ck = (uint32_t)(ks * 2);
            uint32_t a[2][4];
            ldsm4(a[0], smx(As, rowA[0], rmA[0], ck + hiA));
            ldsm4(a[1], smx(As, rowA[1], rmA[1], ck + hiA));
#pragma unroll
            for (int p = 0; p < 2; p++) {
                uint32_t bb1[4], bb3[4];
                ldsm4(bb1, smx(B1s, rowB[p], rmB[p], ck + cselB)); cvt4(bb1);
                ldsm4(bb3, smx(B3s, rowB[p], rmB[p], ck + cselB)); cvt4(bb3);
#pragma unroll
                for (int mi = 0; mi < 2; mi++) {
                    mma8(c1[mi][2 * p],     a[mi], bb1[0], bb1[1]);
                    mma8(c1[mi][2 * p + 1], a[mi], bb1[2], bb1[3]);
                    mma8(c3[mi][2 * p],     a[mi], bb3[0], bb3[1]);
                    mma8(c3[mi][2 * p + 1], a[mi], bb3[2], bb3[3]);
                }
            }
        }
        if (kc + 2 < HH / 32) {
            int s2 = s + 2; if (s2 >= 3) s2 -= 3;
            g1_load(sbase + (uint32_t)s2 * G1_STAGE, kc + 2, tid, s_tok, g_xr, w1r, w3r);
        }
        CP_COMMIT();
        if (++s == 3) s = 0;
    }

    // epilogue: silu(p1)*p3, rounded to tf32, -> g_h
    size_t hrow_base = (size_t)e * TT + m0;
#pragma unroll
    for (int mi = 0; mi < 2; mi++) {
        int lr = wm * 32 + mi * 16 + (lane >> 2);
#pragma unroll
        for (int ni = 0; ni < 4; ni++) {
            int lc = wn * 32 + ni * 8 + (lane & 3) * 2;
            float v0 = rnd_tf32(silu(c1[mi][ni][0]) * c3[mi][ni][0]);
            float v1 = rnd_tf32(silu(c1[mi][ni][1]) * c3[mi][ni][1]);
            float v2 = rnd_tf32(silu(c1[mi][ni][2]) * c3[mi][ni][2]);
            float v3 = rnd_tf32(silu(c1[mi][ni][3]) * c3[mi][ni][3]);
            *(float2*)&g_h[(hrow_base + lr)     * FF + f0 + lc] = make_float2(v0, v1);
            *(float2*)&g_h[(hrow_base + lr + 8) * FF + f0 + lc] = make_float2(v2, v3);
        }
    }
}

// ======== GEMM2: out += gate * (h w2^T) ========
// 256 threads, block tile 128x128, warps 2M x 4N, warp tile 64x32.
static constexpr int G2_STAGE = 2 * 16384;
static constexpr int SMEM2 = 3 * G2_STAGE + 1024;    // 99328

DEVI void g2_load(uint32_t st, int kc, int tid, const float* ha, const float* w2r)
{
#pragma unroll
    for (int p = 0; p < 8; p++) {
        int within = tid + 256 * (p & 3);
        int row = within >> 3, ch = within & 7;
        uint32_t dst = st + (uint32_t)(p >> 2) * 16384u
                     + (uint32_t)row * 128u + ((uint32_t)(ch ^ (row & 7)) << 4);
        const float* src = (p < 4) ? ha + (size_t)row * FF + kc * 32 + ch * 4
                                   : w2r + (size_t)row * FF + kc * 32 + ch * 4;
        cp16(dst, src);
    }
}

__global__ void __launch_bounds__(256, 2) moe_gemm2(
    const float* __restrict__ w2, float* __restrict__ out)
{
    int e   = blockIdx.z;
    int cnt = g_cnt[e];
    int m0  = blockIdx.x * 128;
    if (m0 >= cnt) return;
    int h0  = blockIdx.y * 128;

    extern __shared__ char sm[];
    uint32_t sbase = smem_u32(sm);
    int*   s_tok  = (int*)(sm + 3 * G2_STAGE);
    float* s_gate = (float*)(sm + 3 * G2_STAGE + 512);

    int tid = threadIdx.x, wid = tid >> 5, lane = tid & 31;
    int wm = wid & 1, wn = wid >> 1;

    if (tid < 128) {
        int slot = m0 + tid;
        int idx  = e * TT + (slot < cnt ? slot : 0);
        s_tok[tid]  = g_perm[idx];
        s_gate[tid] = g_gate[idx];
    }
    __syncthreads();

    const float* ha  = &g_h[((size_t)e * TT + m0) * FF];
    const float* w2r = w2 + (size_t)e * HH * FF + (size_t)h0 * FF;

    g2_load(sbase, 0, tid, ha, w2r);
    CP_COMMIT();
    g2_load(sbase + G2_STAGE, 1, tid, ha, w2r);
    CP_COMMIT();

    uint32_t hiA = (uint32_t)(lane >> 4);
    uint32_t cselB = (uint32_t)((lane >> 3) & 1);
    uint32_t rowA[4], rmA[4], rowB[2], rmB[2];
#pragma unroll
    for (int mi = 0; mi < 4; mi++) {
        int r = wm * 64 + mi * 16 + (lane & 15);
        rowA[mi] = (uint32_t)r * 128u; rmA[mi] = (uint32_t)(r & 7);
    }
#pragma unroll
    for (int p = 0; p < 2; p++) {
        int n = wn * 32 + p * 16 + (lane & 7) + ((lane >> 4) << 3);
        rowB[p] = (uint32_t)n * 128u; rmB[p] = (uint32_t)(n & 7);
    }

    float cc[4][4][4];
#pragma unroll
    for (int i = 0; i < 4; i++)
#pragma unroll
        for (int j = 0; j < 4; j++)
#pragma unroll
            for (int k = 0; k < 4; k++) cc[i][j][k] = 0.f;

    int s = 0;
    for (int kc = 0; kc < FF / 32; kc++) {
        CP_WAIT1();
        __syncthreads();
        uint32_t As = sbase + (uint32_t)s * G2_STAGE;
        uint32_t Bs = As + 16384u;
#pragma unroll
        for (int ks = 0; ks < 4; ks++) {
            uint32_t ck = (uint32_t)(ks * 2);
            uint32_t a[4][4];
#pragma unroll
            for (int mi = 0; mi < 4; mi++)
                ldsm4(a[mi], smx(As, rowA[mi], rmA[mi], ck + hiA));
#pragma unroll
            for (int p = 0; p < 2; p++) {
                uint32_t bb[4];
                ldsm4(bb, smx(Bs, rowB[p], rmB[p], ck + cselB)); cvt4(bb);
#pragma unroll
                for (int mi = 0; mi < 4; mi++) {
                    mma8(cc[mi][2 * p],     a[mi], bb[0], bb[1]);
                    mma8(cc[mi][2 * p + 1], a[mi], bb[2], bb[3]);
                }
            }
        }
        if (kc + 2 < FF / 32) {
            int s2 = s + 2; if (s2 >= 3) s2 -= 3;
            g2_load(sbase + (uint32_t)s2 * G2_STAGE, kc + 2, tid, ha, w2r);
        }
        CP_COMMIT();
        if (++s == 3) s = 0;
    }

    // epilogue: scatter-add with gate weights
#pragma unroll
    for (int mi = 0; mi < 4; mi++) {
        int lr0 = wm * 64 + mi * 16 + (lane >> 2);
        int lr1 = lr0 + 8;
        bool v0 = (m0 + lr0) < cnt, v1 = (m0 + lr1) < cnt;
        int   t0 = s_tok[lr0],  t1 = s_tok[lr1];
        float gg0 = s_gate[lr0], gg1 = s_gate[lr1];
        float* o0 = out + (size_t)t0 * HH + h0;
        float* o1 = out + (size_t)t1 * HH + h0;
#pragma unroll
        for (int ni = 0; ni < 4; ni++) {
            int lc = wn * 32 + ni * 8 + (lane & 3) * 2;
            if (v0) {
                atomicAdd(&o0[lc],     gg0 * cc[mi][ni][0]);
                atomicAdd(&o0[lc + 1], gg0 * cc[mi][ni][1]);
            }
            if (v1) {
                atomicAdd(&o1[lc],     gg1 * cc[mi][ni][2]);
                atomicAdd(&o1[lc + 1], gg1 * cc[mi][ni][3]);
            }
        }
    }
}

// ======== launch ========
extern "C" void kernel_launch(void* const* d_in, const int* in_sizes, int n_in,
                              void* d_out, int out_size)
{
    (void)in_sizes; (void)n_in; (void)out_size;
    const float* x  = (const float*)d_in[0];
    const float* wr = (const float*)d_in[1];
    const float* w1 = (const float*)d_in[2];
    const float* w2 = (const float*)d_in[3];
    const float* w3 = (const float*)d_in[4];
    float* out    = (float*)d_out;
    float* logits = out + (size_t)TT * HH;

    cudaFuncSetAttribute(moe_gemm1, cudaFuncAttributeMaxDynamicSharedMemorySize, SMEM1);
    cudaFuncSetAttribute(moe_gemm2, cudaFuncAttributeMaxDynamicSharedMemorySize, SMEM2);

    cudaMemsetAsync(out, 0, (size_t)TT * HH * sizeof(float));
    moe_zero<<<1, 32>>>();
    moe_round_x<<<TT * HH / 1024, 256>>>(x);
    moe_router<<<64, 128>>>(x, wr, logits);
    moe_gemm1<<<dim3(32, 32, EE), 512, SMEM1>>>(w1, w3);
    moe_gemm2<<<dim3(32, 8, EE), 256, SMEM2>>>(w2, out);
}

// round 5
// speedup vs baseline: 1.2603x; 1.1075x over previous
#include <cuda_runtime.h>
#include <cstdint>

// ======== fixed problem dims ========
static constexpr int TT = 4096;
static constexpr int HH = 1024;
static constexpr int FF = 4096;
static constexpr int EE = 8;

// ======== device scratch ========
__device__ int   g_cnt[EE];
__device__ int   g_perm[EE * TT];
__device__ float g_gate[EE * TT];
__device__ float g_xr[(size_t)TT * HH];       // tf32-rounded x
__device__ float g_h[(size_t)EE * TT * FF];   // tf32-rounded intermediate

#define DEVI __device__ __forceinline__

DEVI uint32_t smem_u32(const void* p) {
    uint32_t a;
    asm("{ .reg .u64 t; cvta.to.shared.u64 t, %1; cvt.u32.u64 %0, t; }" : "=r"(a) : "l"(p));
    return a;
}

DEVI void ldsm4(uint32_t* r, uint32_t addr) {
    asm volatile("ldmatrix.sync.aligned.m8n8.x4.shared.b16 {%0,%1,%2,%3}, [%4];"
        : "=r"(r[0]), "=r"(r[1]), "=r"(r[2]), "=r"(r[3]) : "r"(addr));
}
DEVI void cvt4(uint32_t* r) {
#pragma unroll
    for (int i = 0; i < 4; i++) asm("cvt.rna.tf32.f32 %0, %0;" : "+r"(r[i]));
}
DEVI float rnd_tf32(float f) {
    uint32_t u;
    asm("cvt.rna.tf32.f32 %0, %1;" : "=r"(u) : "f"(f));
    return __uint_as_float(u);
}

DEVI void mma8(float* d, const uint32_t* a, uint32_t b0, uint32_t b1) {
    asm volatile(
        "mma.sync.aligned.m16n8k8.row.col.f32.tf32.tf32.f32 "
        "{%0,%1,%2,%3}, {%4,%5,%6,%7}, {%8,%9}, {%0,%1,%2,%3};"
        : "+f"(d[0]), "+f"(d[1]), "+f"(d[2]), "+f"(d[3])
        : "r"(a[0]), "r"(a[1]), "r"(a[2]), "r"(a[3]), "r"(b0), "r"(b1));
}

DEVI void cp16(uint32_t dst, const void* src) {
    asm volatile("cp.async.cg.shared.global [%0], [%1], 16;" :: "r"(dst), "l"(src) : "memory");
}
#define CP_COMMIT() asm volatile("cp.async.commit_group;" ::: "memory")
#define CP_WAIT1()  asm volatile("cp.async.wait_group 1;" ::: "memory")

DEVI uint32_t smx(uint32_t base, uint32_t rowoff, uint32_t rmask, uint32_t chunk) {
    return base + rowoff + ((chunk ^ rmask) << 4);
}

DEVI float silu(float v) { return v / (1.f + __expf(-v)); }

// ======== kernel 0: zero counters ========
__global__ void moe_zero() {
    if (threadIdx.x < EE) g_cnt[threadIdx.x] = 0;
}

// ======== kernel 0b: pre-round x to tf32 ========
__global__ void __launch_bounds__(256) moe_round_x(const float* __restrict__ x) {
    int i = blockIdx.x * 256 + threadIdx.x;
    float4 v = ((const float4*)x)[i];
    v.x = rnd_tf32(v.x); v.y = rnd_tf32(v.y); v.z = rnd_tf32(v.z); v.w = rnd_tf32(v.w);
    ((float4*)g_xr)[i] = v;
}

// ======== kernel 1: router ========
__global__ void __launch_bounds__(128) moe_router(
    const float* __restrict__ x, const float* __restrict__ wr, float* __restrict__ logits)
{
    __shared__ float swr[EE * HH];
    for (int i = threadIdx.x; i < EE * HH; i += 128) {
        int col = i >> 3, e = i & 7;
        swr[i] = wr[e * HH + col];
    }
    __syncthreads();

    int nwarp = gridDim.x * 4;
    int warp  = blockIdx.x * 4 + (threadIdx.x >> 5);
    int lane  = threadIdx.x & 31;

    for (int t = warp; t < TT; t += nwarp) {
        float acc[EE];
#pragma unroll
        for (int e = 0; e < EE; e++) acc[e] = 0.f;
        const float4* xr = (const float4*)(x + (size_t)t * HH);
        for (int i = lane; i < HH / 4; i += 32) {
            float4 v = xr[i];
            int c = i * 4;
#pragma unroll
            for (int e = 0; e < EE; e++)
                acc[e] += v.x * swr[(c + 0) * 8 + e] + v.y * swr[(c + 1) * 8 + e]
                        + v.z * swr[(c + 2) * 8 + e] + v.w * swr[(c + 3) * 8 + e];
        }
#pragma unroll
        for (int e = 0; e < EE; e++) {
#pragma unroll
            for (int o = 16; o > 0; o >>= 1)
                acc[e] += __shfl_xor_sync(0xffffffffu, acc[e], o);
        }
        if (lane == 0) {
            float mx = acc[0];
#pragma unroll
            for (int e = 1; e < EE; e++) mx = fmaxf(mx, acc[e]);
            float p[EE];
#pragma unroll
            for (int e = 0; e < EE; e++) p[e] = __expf(acc[e] - mx);
            int e0 = 0;
#pragma unroll
            for (int e = 1; e < EE; e++) if (p[e] > p[e0]) e0 = e;
            int e1 = (e0 == 0) ? 1 : 0;
#pragma unroll
            for (int e = 0; e < EE; e++) if (e != e0 && p[e] > p[e1]) e1 = e;
            float ws = p[e0] + p[e1];
            float w0 = p[e0] / ws, w1v = p[e1] / ws;
#pragma unroll
            for (int e = 0; e < EE; e++) logits[(size_t)t * EE + e] = acc[e];
            int q0 = atomicAdd(&g_cnt[e0], 1);
            g_perm[e0 * TT + q0] = t; g_gate[e0 * TT + q0] = w0;
            int q1 = atomicAdd(&g_cnt[e1], 1);
            g_perm[e1 * TT + q1] = t; g_gate[e1 * TT + q1] = w1v;
        }
    }
}

// ======== GEMM1: h = silu(X w1^T) * (X w3^T) ========
// 256 threads, block tile M=128 x N=64 (dual-B: smem B = 64 w1 rows + 64 w3 rows).
// Warps 2M x 4N; warp tile 64 x 16 per matrix, dual accum (64 regs). 2 CTAs/SM.
static constexpr int G1_STAGE = 2 * 16384;            // A(128x32) + B(128x32)
static constexpr int SMEM1 = 3 * G1_STAGE + 512;      // 98816

DEVI void g1_load(uint32_t st, int kc, int tid, const int* s_tok,
                  const float* xr, const float* w1r, const float* w3r)
{
#pragma unroll
    for (int p = 0; p < 8; p++) {
        int within = tid + 256 * (p & 3);
        int row = within >> 3, ch = within & 7;
        uint32_t dst = st + (uint32_t)(p >> 2) * 16384u
                     + (uint32_t)row * 128u + ((uint32_t)(ch ^ (row & 7)) << 4);
        const float* src;
        if (p < 4) src = xr + (size_t)s_tok[row] * HH + kc * 32 + ch * 4;
        else       src = (row < 64 ? w1r + (size_t)row * HH
                                   : w3r + (size_t)(row - 64) * HH) + kc * 32 + ch * 4;
        cp16(dst, src);
    }
}

__global__ void __launch_bounds__(256, 2) moe_gemm1(
    const float* __restrict__ w1, const float* __restrict__ w3)
{
    int e   = blockIdx.z;
    int cnt = g_cnt[e];
    int m0  = blockIdx.x * 128;
    if (m0 >= cnt) return;
    int f0  = blockIdx.y * 64;

    extern __shared__ char sm[];
    uint32_t sbase = smem_u32(sm);
    int* s_tok = (int*)(sm + 3 * G1_STAGE);

    int tid = threadIdx.x, wid = tid >> 5, lane = tid & 31;
    int wm = wid & 1, wn = wid >> 1;

    if (tid < 128) {
        int slot = m0 + tid;
        s_tok[tid] = g_perm[e * TT + (slot < cnt ? slot : 0)];
    }
    __syncthreads();

    const float* w1r = w1 + (size_t)e * FF * HH + (size_t)f0 * HH;
    const float* w3r = w3 + (size_t)e * FF * HH + (size_t)f0 * HH;

    g1_load(sbase, 0, tid, s_tok, g_xr, w1r, w3r);
    CP_COMMIT();
    g1_load(sbase + G1_STAGE, 1, tid, s_tok, g_xr, w1r, w3r);
    CP_COMMIT();

    uint32_t hiA   = (uint32_t)(lane >> 4);
    uint32_t cselB = (uint32_t)((lane >> 3) & 1);
    uint32_t rowA[4], rmA[4];
#pragma unroll
    for (int mi = 0; mi < 4; mi++) {
        int r = wm * 64 + mi * 16 + (lane & 15);
        rowA[mi] = (uint32_t)r * 128u; rmA[mi] = (uint32_t)(r & 7);
    }
    int nb1 = wn * 16 + (lane & 7) + ((lane >> 4) << 3);   // w1 rows 0..63
    int nb3 = 64 + nb1;                                     // w3 rows 64..127
    uint32_t rowB1 = (uint32_t)nb1 * 128u, rmB1 = (uint32_t)(nb1 & 7);
    uint32_t rowB3 = (uint32_t)nb3 * 128u, rmB3 = (uint32_t)(nb3 & 7);

    float c1[4][2][4], c3[4][2][4];
#pragma unroll
    for (int i = 0; i < 4; i++)
#pragma unroll
        for (int j = 0; j < 2; j++)
#pragma unroll
            for (int k = 0; k < 4; k++) { c1[i][j][k] = 0.f; c3[i][j][k] = 0.f; }

    int s = 0;
    for (int kc = 0; kc < HH / 32; kc++) {
        CP_WAIT1();
        __syncthreads();
        uint32_t As = sbase + (uint32_t)s * G1_STAGE;
        uint32_t Bs = As + 16384u;
#pragma unroll
        for (int ks = 0; ks < 4; ks++) {
            uint32_t ck = (uint32_t)(ks * 2);
            uint32_t a[4][4];
#pragma unroll
            for (int mi = 0; mi < 4; mi++)
                ldsm4(a[mi], smx(As, rowA[mi], rmA[mi], ck + hiA));
            uint32_t bb1[4], bb3[4];
            ldsm4(bb1, smx(Bs, rowB1, rmB1, ck + cselB)); cvt4(bb1);
            ldsm4(bb3, smx(Bs, rowB3, rmB3, ck + cselB)); cvt4(bb3);
#pragma unroll
            for (int mi = 0; mi < 4; mi++) {
                mma8(c1[mi][0], a[mi], bb1[0], bb1[1]);
                mma8(c1[mi][1], a[mi], bb1[2], bb1[3]);
                mma8(c3[mi][0], a[mi], bb3[0], bb3[1]);
                mma8(c3[mi][1], a[mi], bb3[2], bb3[3]);
            }
        }
        if (kc + 2 < HH / 32) {
            int s2 = s + 2; if (s2 >= 3) s2 -= 3;
            g1_load(sbase + (uint32_t)s2 * G1_STAGE, kc + 2, tid, s_tok, g_xr, w1r, w3r);
        }
        CP_COMMIT();
        if (++s == 3) s = 0;
    }

    // epilogue: silu(p1)*p3, rounded to tf32 -> g_h (no cross-warp exchange)
    size_t hrow_base = (size_t)e * TT + m0;
#pragma unroll
    for (int mi = 0; mi < 4; mi++) {
        int lr = wm * 64 + mi * 16 + (lane >> 2);
#pragma unroll
        for (int ni = 0; ni < 2; ni++) {
            int lc = wn * 16 + ni * 8 + (lane & 3) * 2;
            float v0 = rnd_tf32(silu(c1[mi][ni][0]) * c3[mi][ni][0]);
            float v1 = rnd_tf32(silu(c1[mi][ni][1]) * c3[mi][ni][1]);
            float v2 = rnd_tf32(silu(c1[mi][ni][2]) * c3[mi][ni][2]);
            float v3 = rnd_tf32(silu(c1[mi][ni][3]) * c3[mi][ni][3]);
            *(float2*)&g_h[(hrow_base + lr)     * FF + f0 + lc] = make_float2(v0, v1);
            *(float2*)&g_h[(hrow_base + lr + 8) * FF + f0 + lc] = make_float2(v2, v3);
        }
    }
}

// ======== GEMM2: out += gate * (h w2^T) ========
static constexpr int G2_STAGE = 2 * 16384;
static constexpr int SMEM2 = 3 * G2_STAGE + 1024;    // 99328

DEVI void g2_load(uint32_t st, int kc, int tid, const float* ha, const float* w2r)
{
#pragma unroll
    for (int p = 0; p < 8; p++) {
        int within = tid + 256 * (p & 3);
        int row = within >> 3, ch = within & 7;
        uint32_t dst = st + (uint32_t)(p >> 2) * 16384u
                     + (uint32_t)row * 128u + ((uint32_t)(ch ^ (row & 7)) << 4);
        const float* src = (p < 4) ? ha + (size_t)row * FF + kc * 32 + ch * 4
                                   : w2r + (size_t)row * FF + kc * 32 + ch * 4;
        cp16(dst, src);
    }
}

__global__ void __launch_bounds__(256, 2) moe_gemm2(
    const float* __restrict__ w2, float* __restrict__ out)
{
    int e   = blockIdx.z;
    int cnt = g_cnt[e];
    int m0  = blockIdx.x * 128;
    if (m0 >= cnt) return;
    int h0  = blockIdx.y * 128;

    extern __shared__ char sm[];
    uint32_t sbase = smem_u32(sm);
    int*   s_tok  = (int*)(sm + 3 * G2_STAGE);
    float* s_gate = (float*)(sm + 3 * G2_STAGE + 512);

    int tid = threadIdx.x, wid = tid >> 5, lane = tid & 31;
    int wm = wid & 1, wn = wid >> 1;

    if (tid < 128) {
        int slot = m0 + tid;
        int idx  = e * TT + (slot < cnt ? slot : 0);
        s_tok[tid]  = g_perm[idx];
        s_gate[tid] = g_gate[idx];
    }
    __syncthreads();

    const float* ha  = &g_h[((size_t)e * TT + m0) * FF];
    const float* w2r = w2 + (size_t)e * HH * FF + (size_t)h0 * FF;

    g2_load(sbase, 0, tid, ha, w2r);
    CP_COMMIT();
    g2_load(sbase + G2_STAGE, 1, tid, ha, w2r);
    CP_COMMIT();

    uint32_t hiA   = (uint32_t)(lane >> 4);
    uint32_t cselB = (uint32_t)((lane >> 3) & 1);
    uint32_t rowA[4], rmA[4], rowB[2], rmB[2];
#pragma unroll
    for (int mi = 0; mi < 4; mi++) {
        int r = wm * 64 + mi * 16 + (lane & 15);
        rowA[mi] = (uint32_t)r * 128u; rmA[mi] = (uint32_t)(r & 7);
    }
#pragma unroll
    for (int p = 0; p < 2; p++) {
        int n = wn * 32 + p * 16 + (lane & 7) + ((lane >> 4) << 3);
        rowB[p] = (uint32_t)n * 128u; rmB[p] = (uint32_t)(n & 7);
    }

    float cc[4][4][4];
#pragma unroll
    for (int i = 0; i < 4; i++)
#pragma unroll
        for (int j = 0; j < 4; j++)
#pragma unroll
            for (int k = 0; k < 4; k++) cc[i][j][k] = 0.f;

    int s = 0;
    for (int kc = 0; kc < FF / 32; kc++) {
        CP_WAIT1();
        __syncthreads();
        uint32_t As = sbase + (uint32_t)s * G2_STAGE;
        uint32_t Bs = As + 16384u;
#pragma unroll
        for (int ks = 0; ks < 4; ks++) {
            uint32_t ck = (uint32_t)(ks * 2);
            uint32_t a[4][4];
#pragma unroll
            for (int mi = 0; mi < 4; mi++)
                ldsm4(a[mi], smx(As, rowA[mi], rmA[mi], ck + hiA));
#pragma unroll
            for (int p = 0; p < 2; p++) {
                uint32_t bb[4];
                ldsm4(bb, smx(Bs, rowB[p], rmB[p], ck + cselB)); cvt4(bb);
#pragma unroll
                for (int mi = 0; mi < 4; mi++) {
                    mma8(cc[mi][2 * p],     a[mi], bb[0], bb[1]);
                    mma8(cc[mi][2 * p + 1], a[mi], bb[2], bb[3]);
                }
            }
        }
        if (kc + 2 < FF / 32) {
            int s2 = s + 2; if (s2 >= 3) s2 -= 3;
            g2_load(sbase + (uint32_t)s2 * G2_STAGE, kc + 2, tid, ha, w2r);
        }
        CP_COMMIT();
        if (++s == 3) s = 0;
    }

    // epilogue: scatter-add with gate weights
#pragma unroll
    for (int mi = 0; mi < 4; mi++) {
        int lr0 = wm * 64 + mi * 16 + (lane >> 2);
        int lr1 = lr0 + 8;
        bool v0 = (m0 + lr0) < cnt, v1 = (m0 + lr1) < cnt;
        int   t0 = s_tok[lr0],  t1 = s_tok[lr1];
        float gg0 = s_gate[lr0], gg1 = s_gate[lr1];
        float* o0 = out + (size_t)t0 * HH + h0;
        float* o1 = out + (size_t)t1 * HH + h0;
#pragma unroll
        for (int ni = 0; ni < 4; ni++) {
            int lc = wn * 32 + ni * 8 + (lane & 3) * 2;
            if (v0) {
                atomicAdd(&o0[lc],     gg0 * cc[mi][ni][0]);
                atomicAdd(&o0[lc + 1], gg0 * cc[mi][ni][1]);
            }
            if (v1) {
                atomicAdd(&o1[lc],     gg1 * cc[mi][ni][2]);
                atomicAdd(&o1[lc + 1], gg1 * cc[mi][ni][3]);
            }
        }
    }
}

// ======== launch ========
extern "C" void kernel_launch(void* const* d_in, const int* in_sizes, int n_in,
                              void* d_out, int out_size)
{
    (void)in_sizes; (void)n_in; (void)out_size;
    const float* x  = (const float*)d_in[0];
    const float* wr = (const float*)d_in[1];
    const float* w1 = (const float*)d_in[2];
    const float* w2 = (const float*)d_in[3];
    const float* w3 = (const float*)d_in[4];
    float* out    = (float*)d_out;
    float* logits = out + (size_t)TT * HH;

    cudaFuncSetAttribute(moe_gemm1, cudaFuncAttributeMaxDynamicSharedMemorySize, SMEM1);
    cudaFuncSetAttribute(moe_gemm2, cudaFuncAttributeMaxDynamicSharedMemorySize, SMEM2);

    cudaMemsetAsync(out, 0, (size_t)TT * HH * sizeof(float));
    moe_zero<<<1, 32>>>();
    moe_round_x<<<TT * HH / 1024, 256>>>(x);
    moe_router<<<64, 128>>>(x, wr, logits);
    moe_gemm1<<<dim3(32, 64, EE), 256, SMEM1>>>(w1, w3);
    moe_gemm2<<<dim3(32, 8, EE), 256, SMEM2>>>(w2, out);
}